// round 6
// baseline (speedup 1.0000x reference)
#include <cuda_runtime.h>
#include <cuda_bf16.h>

#define NUM_G       32768
#define FIN_BLOCKS  128     // tail blocks that perform the finalize
#define FIN_THREADS 256     // FIN_BLOCKS * FIN_THREADS == NUM_G

// Scratch (allocation-free __device__ globals; zero-initialized at load).
// INVARIANT: all scratch is zero at kernel entry; the finalize tail restores
// everything to zero, so every graph replay sees identical state.
__device__ float4   g_acc[NUM_G];   // {tsum, psum, S = sum exp(t)*p, count}
__device__ float    g_total;
__device__ int      g_nvalid;
__device__ unsigned g_done;
__device__ unsigned g_done2;

// Pure-FMA exp: exp(x) = 2^(x*log2e). Magic-number round, deg-5 poly on [-0.5,0.5].
// Rel err ~2e-6; avoids the MUFU.EX2 throughput wall.
__device__ __forceinline__ float fexp(float x) {
    const float L2E = 1.4426950408889634f;
    float z  = fmaf(x, L2E, 12582912.0f);           // 1.5*2^23 magic
    int   n  = __float_as_int(z) - 0x4B400000;      // round(x*log2e) as int
    float zi = z - 12582912.0f;                     // round(x*log2e) as float
    float f  = fmaf(x, L2E, -zi);                   // frac in [-0.5, 0.5]
    float p  = 1.3333558146e-3f;
    p = fmaf(p, f, 9.6181291076e-3f);
    p = fmaf(p, f, 5.5504108664e-2f);
    p = fmaf(p, f, 2.4022650696e-1f);
    p = fmaf(p, f, 6.9314718056e-1f);
    p = fmaf(p, f, 1.0f);
    return __int_as_float(__float_as_int(p) + (n << 23));
}

// One 16-byte vectorized L2 reduction: {tsum += te, psum += pe, S += te*p, count += 1}
__device__ __forceinline__ void red4(float4* a, float te, float pe, float s) {
    asm volatile("red.global.add.v4.f32 [%0], {%1, %2, %3, %4};"
                 :: "l"(a), "f"(te), "f"(pe), "f"(s), "f"(1.0f) : "memory");
}

// Fused: accumulation pass + (in the last FIN_BLOCKS-to-finish blocks) the
// per-group finalize, global reduce, output write, and scratch reset.
__global__ void k_fused(const float4* __restrict__ p4,
                        const float4* __restrict__ t4,
                        const int4*  __restrict__ g4,
                        int nv, float* __restrict__ out) {
    int half = nv >> 1;
    int i = blockIdx.x * blockDim.x + threadIdx.x;

    // ---- Phase 1: accumulate (8 elements per thread, 1 red.v4 each) ----
    if (i < half) {
        float4 pA = p4[i], pB = p4[i + half];
        float4 tA = t4[i], tB = t4[i + half];
        int4   gA = g4[i], gB = g4[i + half];

        float ax = fexp(tA.x), ay = fexp(tA.y), az = fexp(tA.z), aw = fexp(tA.w);
        float bx = fexp(tB.x), by = fexp(tB.y), bz = fexp(tB.z), bw = fexp(tB.w);

        red4(&g_acc[gA.x], ax, fexp(pA.x), ax * pA.x);
        red4(&g_acc[gA.y], ay, fexp(pA.y), ay * pA.y);
        red4(&g_acc[gA.z], az, fexp(pA.z), az * pA.z);
        red4(&g_acc[gA.w], aw, fexp(pA.w), aw * pA.w);
        red4(&g_acc[gB.x], bx, fexp(pB.x), bx * pB.x);
        red4(&g_acc[gB.y], by, fexp(pB.y), by * pB.y);
        red4(&g_acc[gB.z], bz, fexp(pB.z), bz * pB.z);
        red4(&g_acc[gB.w], bw, fexp(pB.w), bw * pB.w);
    }

    // ---- Ticket: last FIN_BLOCKS blocks to finish become the finalizers ----
    __shared__ unsigned s_ticket;
    __syncthreads();                      // all reds in this block issued
    if (threadIdx.x == 0) {
        __threadfence();                  // publish this block's reds (gpu scope)
        s_ticket = atomicAdd(&g_done, 1u);
    }
    __syncthreads();
    unsigned ticket = s_ticket;
    unsigned nblk = gridDim.x;
    if (ticket < nblk - FIN_BLOCKS) return;   // not a finalizer

    // ---- Phase 2: wait for ALL blocks' accumulation to be visible ----
    if (threadIdx.x == 0) {
        while (*(volatile unsigned*)&g_done != nblk) { }
        __threadfence();                  // acquire: all reds now visible
    }
    __syncthreads();

    // Each finalize block owns a 256-group slice: 1 group per thread.
    unsigned slice = ticket - (nblk - FIN_BLOCKS);      // 0..FIN_BLOCKS-1
    int g = (int)(slice * FIN_THREADS + threadIdx.x);

    float4 a = g_acc[g];
    g_acc[g] = make_float4(0.f, 0.f, 0.f, 0.f);         // restore zero for next replay
    bool valid = (a.w >= 1.5f);                         // count >= 2
    float s = valid ? (logf(a.y) - a.z / a.x) : 0.0f;   // loss_g = lse - S/tsum

    // block reduce (loss, valid count)
    unsigned b = __ballot_sync(0xffffffffu, valid);
    #pragma unroll
    for (int o = 16; o > 0; o >>= 1) s += __shfl_down_sync(0xffffffffu, s, o);
    __shared__ float sh[8];
    __shared__ int   shc[8];
    int lane = threadIdx.x & 31, wid = threadIdx.x >> 5;
    if (lane == 0) { sh[wid] = s; shc[wid] = __popc(b); }
    __syncthreads();
    if (wid == 0) {
        s = (lane < (FIN_THREADS >> 5)) ? sh[lane] : 0.0f;
        int c = (lane < (FIN_THREADS >> 5)) ? shc[lane] : 0;
        #pragma unroll
        for (int o = 4; o > 0; o >>= 1) {
            s += __shfl_down_sync(0xffffffffu, s, o);
            c += __shfl_down_sync(0xffffffffu, c, o);
        }
        if (lane == 0) {
            atomicAdd(&g_total, s);
            atomicAdd(&g_nvalid, c);
            __threadfence();
            unsigned t2 = atomicAdd(&g_done2, 1u);
            if (t2 == FIN_BLOCKS - 1) {               // last finalizer writes output
                int   nvg = *(volatile int*)&g_nvalid;
                float tt  = *(volatile float*)&g_total;
                out[0] = (nvg > 0) ? (tt / (float)nvg) : 0.0f;
                g_total = 0.0f; g_nvalid = 0;          // reset for next replay
                g_done = 0u;   g_done2 = 0u;
            }
        }
    }
}

extern "C" void kernel_launch(void* const* d_in, const int* in_sizes, int n_in,
                              void* d_out, int out_size) {
    const float* pred = (const float*)d_in[0];
    const float* targ = (const float*)d_in[1];
    const int*   gid  = (const int*)d_in[2];
    float* out = (float*)d_out;
    int n  = in_sizes[0];
    int nv = n / 4;                       // n is a multiple of 4 (4,194,304)
    int gb = (nv / 2 + 255) / 256;        // 2048 blocks (>= FIN_BLOCKS)

    k_fused<<<gb, 256>>>((const float4*)pred, (const float4*)targ,
                         (const int4*)gid, nv, out);
}

// round 7
// speedup vs baseline: 1.1477x; 1.1477x over previous
#include <cuda_runtime.h>
#include <cuda_bf16.h>

#define NUM_G 32768

// Scratch (allocation-free __device__ globals; zero-initialized at load).
// INVARIANT: all scratch is zero at kernel_launch entry; k_fin restores
// everything to zero, so every graph replay sees identical state.
__device__ float4   g_acc[NUM_G];   // {tsum, psum, S = sum exp(t)*p, count}
__device__ float    g_total;
__device__ int      g_nvalid;
__device__ unsigned g_done;

// Pure-FMA exp: exp(x) = 2^(x*log2e). Magic-number round, deg-5 poly on [-0.5,0.5].
// Rel err ~2e-6; avoids the MUFU.EX2 throughput wall.
__device__ __forceinline__ float fexp(float x) {
    const float L2E = 1.4426950408889634f;
    float z  = fmaf(x, L2E, 12582912.0f);           // 1.5*2^23 magic
    int   n  = __float_as_int(z) - 0x4B400000;      // round(x*log2e) as int
    float zi = z - 12582912.0f;                     // round(x*log2e) as float
    float f  = fmaf(x, L2E, -zi);                   // frac in [-0.5, 0.5]
    float p  = 1.3333558146e-3f;
    p = fmaf(p, f, 9.6181291076e-3f);
    p = fmaf(p, f, 5.5504108664e-2f);
    p = fmaf(p, f, 2.4022650696e-1f);
    p = fmaf(p, f, 6.9314718056e-1f);
    p = fmaf(p, f, 1.0f);
    return __int_as_float(__float_as_int(p) + (n << 23));
}

// One 16-byte vectorized L2 reduction: {tsum += te, psum += pe, S += te*p, count += 1}
__device__ __forceinline__ void red4(float4* a, float te, float pe, float s) {
    asm volatile("red.global.add.v4.f32 [%0], {%1, %2, %3, %4};"
                 :: "l"(a), "f"(te), "f"(pe), "f"(s), "f"(1.0f) : "memory");
}

// Streaming float4 / int4 loads (evict-first: keep L2 capacity for the atomics).
__device__ __forceinline__ float4 ldcs4(const float4* p) {
    float4 v;
    asm volatile("ld.global.cs.v4.f32 {%0,%1,%2,%3}, [%4];"
                 : "=f"(v.x), "=f"(v.y), "=f"(v.z), "=f"(v.w) : "l"(p));
    return v;
}
__device__ __forceinline__ int4 ldcs4i(const int4* p) {
    int4 v;
    asm volatile("ld.global.cs.v4.b32 {%0,%1,%2,%3}, [%4];"
                 : "=r"(v.x), "=r"(v.y), "=r"(v.z), "=r"(v.w) : "l"(p));
    return v;
}

// Pass 1: per-group sums of exp(t), exp(p), exp(t)*p, count — ONE red.v4 per element.
__global__ void k_accum(const float4* __restrict__ p4,
                        const float4* __restrict__ t4,
                        const int4*  __restrict__ g4, int nv) {
    int half = nv >> 1;
    int i = blockIdx.x * blockDim.x + threadIdx.x;
    if (i >= half) return;
    float4 pA = ldcs4(&p4[i]), pB = ldcs4(&p4[i + half]);
    float4 tA = ldcs4(&t4[i]), tB = ldcs4(&t4[i + half]);
    int4   gA = ldcs4i(&g4[i]), gB = ldcs4i(&g4[i + half]);

    float ax = fexp(tA.x), ay = fexp(tA.y), az = fexp(tA.z), aw = fexp(tA.w);
    float bx = fexp(tB.x), by = fexp(tB.y), bz = fexp(tB.z), bw = fexp(tB.w);

    red4(&g_acc[gA.x], ax, fexp(pA.x), ax * pA.x);
    red4(&g_acc[gA.y], ay, fexp(pA.y), ay * pA.y);
    red4(&g_acc[gA.z], az, fexp(pA.z), az * pA.z);
    red4(&g_acc[gA.w], aw, fexp(pA.w), aw * pA.w);
    red4(&g_acc[gB.x], bx, fexp(pB.x), bx * pB.x);
    red4(&g_acc[gB.y], by, fexp(pB.y), by * pB.y);
    red4(&g_acc[gB.z], bz, fexp(pB.z), bz * pB.z);
    red4(&g_acc[gB.w], bw, fexp(pB.w), bw * pB.w);
}

// Pass 2 (PDL secondary): per-group loss_g = log(psum) - S/tsum (0 when count<2),
// global reduce, output write, scratch reset. 2 groups per thread, loads issued
// up front for MLP. 64 blocks x 256 threads covers all 32768 groups.
__global__ void k_fin(float* __restrict__ out) {
    cudaGridDependencySynchronize();     // wait for k_accum's reds to be visible

    int base = blockIdx.x * 512 + threadIdx.x;     // two groups: base, base+256
    float4 a0 = __ldcg(&g_acc[base]);
    float4 a1 = __ldcg(&g_acc[base + 256]);
    g_acc[base]       = make_float4(0.f, 0.f, 0.f, 0.f);   // reset for next replay
    g_acc[base + 256] = make_float4(0.f, 0.f, 0.f, 0.f);

    bool v0 = (a0.w >= 1.5f), v1 = (a1.w >= 1.5f);  // count >= 2
    float s = 0.0f;
    if (v0) s  = logf(a0.y) - a0.z / a0.x;
    if (v1) s += logf(a1.y) - a1.z / a1.x;
    int c = (int)v0 + (int)v1;

    // block reduce (loss, valid count)
    #pragma unroll
    for (int o = 16; o > 0; o >>= 1) {
        s += __shfl_down_sync(0xffffffffu, s, o);
        c += __shfl_down_sync(0xffffffffu, c, o);
    }
    __shared__ float sh[8];
    __shared__ int   shc[8];
    int lane = threadIdx.x & 31, wid = threadIdx.x >> 5;
    if (lane == 0) { sh[wid] = s; shc[wid] = c; }
    __syncthreads();
    if (wid == 0) {
        s = (lane < 8) ? sh[lane] : 0.0f;
        c = (lane < 8) ? shc[lane] : 0;
        #pragma unroll
        for (int o = 4; o > 0; o >>= 1) {
            s += __shfl_down_sync(0xffffffffu, s, o);
            c += __shfl_down_sync(0xffffffffu, c, o);
        }
        if (lane == 0) {
            atomicAdd(&g_total, s);
            atomicAdd(&g_nvalid, c);
            __threadfence();
            unsigned t = atomicAdd(&g_done, 1u);
            if (t == gridDim.x - 1) {               // last block writes output
                int   nvg = *(volatile int*)&g_nvalid;
                float tt  = *(volatile float*)&g_total;
                out[0] = (nvg > 0) ? (tt / (float)nvg) : 0.0f;
                g_total = 0.0f; g_nvalid = 0; g_done = 0u;   // reset for next replay
            }
        }
    }
}

extern "C" void kernel_launch(void* const* d_in, const int* in_sizes, int n_in,
                              void* d_out, int out_size) {
    const float* pred = (const float*)d_in[0];
    const float* targ = (const float*)d_in[1];
    const int*   gid  = (const int*)d_in[2];
    float* out = (float*)d_out;
    int n  = in_sizes[0];
    int nv = n / 4;                       // n is a multiple of 4 (4,194,304)
    int gb = (nv / 2 + 255) / 256;        // 2048 blocks

    k_accum<<<gb, 256>>>((const float4*)pred, (const float4*)targ,
                         (const int4*)gid, nv);

    // PDL launch: k_fin's launch/prologue overlaps k_accum's tail; the
    // cudaGridDependencySynchronize() inside gates the actual data read.
    cudaLaunchConfig_t cfg = {};
    cfg.gridDim  = dim3(64);
    cfg.blockDim = dim3(256);
    cfg.stream   = 0;
    cudaLaunchAttribute attr[1];
    attr[0].id = cudaLaunchAttributeProgrammaticStreamSerialization;
    attr[0].val.programmaticStreamSerializationAllowed = 1;
    cfg.attrs    = attr;
    cfg.numAttrs = 1;
    cudaLaunchKernelEx(&cfg, k_fin, out);
}